// round 8
// baseline (speedup 1.0000x reference)
#include <cuda_runtime.h>
#include <cstdint>

#define NBATCH 4
#define NQ 2048
#define NF 16384
#define CDIM 768
#define SCALEF 0.57735026918962576f

// ---- GEMM tiling ----
#define BM 128
#define BN 128
#define BK 32
#define STAGES 3
#define LDT 36
#define TILE_FLOATS (BM * LDT)
#define STAGE_FLOATS (2 * TILE_FLOATS)
#define GEMM_SMEM (STAGES * STAGE_FLOATS * 4)
#define NCH (NF / BK)

__device__ __align__(16) float4 g_qp[NBATCH * NQ];
__device__ __align__(16) float4 g_kp[NBATCH * NF];
__device__ __align__(16) float g_p[(size_t)NBATCH * NQ * NF];
__device__ __align__(16) float g_vt[(size_t)NBATCH * CDIM * NF];
__device__ float g_iden[NBATCH * NQ];

__device__ __forceinline__ uint32_t smem_u32(const void* p) {
    uint32_t a;
    asm("{ .reg .u64 t; cvta.to.shared.u64 t, %1; cvt.u32.u64 %0, t; }" : "=r"(a) : "l"(p));
    return a;
}
__device__ __forceinline__ float tf32r(float x) {
    uint32_t u;
    asm("cvt.rna.tf32.f32 %0, %1;" : "=r"(u) : "f"(x));
    return __uint_as_float(u);
}
__device__ __forceinline__ uint32_t lds32(uint32_t a) {
    uint32_t v;
    asm volatile("ld.shared.b32 %0, [%1];" : "=r"(v) : "r"(a));
    return v;
}
__device__ __forceinline__ void cp_async16(uint32_t saddr, const float* gaddr) {
    asm volatile("cp.async.cg.shared.global [%0], [%1], 16;" :: "r"(saddr), "l"(gaddr));
}
#define CP_COMMIT() asm volatile("cp.async.commit_group;" ::: "memory")
#define CP_WAIT2()  asm volatile("cp.async.wait_group 2;" ::: "memory")

__device__ __forceinline__ void mma_tf32(float* d, const uint32_t* a, const uint32_t* b) {
    asm volatile(
        "mma.sync.aligned.m16n8k8.row.col.f32.tf32.tf32.f32 "
        "{%0,%1,%2,%3}, {%4,%5,%6,%7}, {%8,%9}, {%0,%1,%2,%3};"
        : "+f"(d[0]), "+f"(d[1]), "+f"(d[2]), "+f"(d[3])
        : "r"(a[0]), "r"(a[1]), "r"(a[2]), "r"(a[3]), "r"(b[0]), "r"(b[1]));
}

// ---- Kernel 1: 3x3 projections + ReLU (q pre-scaled) ----
__global__ void proj_kernel(const float* __restrict__ q, const float* __restrict__ k,
                            const float* __restrict__ W1, const float* __restrict__ b1,
                            const float* __restrict__ W2, const float* __restrict__ b2) {
    int i = blockIdx.x * blockDim.x + threadIdx.x;
    const int nq = NBATCH * NQ, nf = NBATCH * NF;
    if (i < nq) {
        float x0 = q[3 * i], x1 = q[3 * i + 1], x2 = q[3 * i + 2];
        float4 o;
        o.x = SCALEF * fmaxf(0.f, fmaf(W1[0], x0, fmaf(W1[1], x1, fmaf(W1[2], x2, b1[0]))));
        o.y = SCALEF * fmaxf(0.f, fmaf(W1[3], x0, fmaf(W1[4], x1, fmaf(W1[5], x2, b1[1]))));
        o.z = SCALEF * fmaxf(0.f, fmaf(W1[6], x0, fmaf(W1[7], x1, fmaf(W1[8], x2, b1[2]))));
        o.w = 0.f;
        g_qp[i] = o;
    } else if (i < nq + nf) {
        int j = i - nq;
        float x0 = k[3 * j], x1 = k[3 * j + 1], x2 = k[3 * j + 2];
        float4 o;
        o.x = fmaxf(0.f, fmaf(W2[0], x0, fmaf(W2[1], x1, fmaf(W2[2], x2, b2[0]))));
        o.y = fmaxf(0.f, fmaf(W2[3], x0, fmaf(W2[4], x1, fmaf(W2[5], x2, b2[1]))));
        o.z = fmaxf(0.f, fmaf(W2[6], x0, fmaf(W2[7], x1, fmaf(W2[8], x2, b2[2]))));
        o.w = 0.f;
        g_kp[j] = o;
    }
}

// ---- Kernel 2: E = exp(qp.kp) (tf32-rounded) + 1/den. 8 rows/block. ----
__global__ void __launch_bounds__(256) exp_kernel() {
    const int m0 = blockIdx.x * 8, b = blockIdx.y;
    const int tid = threadIdx.x;
    float4 qv[8];
    #pragma unroll
    for (int r = 0; r < 8; ++r) qv[r] = g_qp[b * NQ + m0 + r];
    const float4* __restrict__ kp = g_kp + b * NF;
    float* __restrict__ pbase = g_p + ((size_t)b * NQ + m0) * NF;

    float part[8];
    #pragma unroll
    for (int r = 0; r < 8; ++r) part[r] = 0.f;

    for (int i = tid; i < NF; i += 256) {
        float4 kv = kp[i];
        #pragma unroll
        for (int r = 0; r < 8; ++r) {
            float e = __expf(qv[r].x * kv.x + qv[r].y * kv.y + qv[r].z * kv.z);
            part[r] += e;
            pbase[(size_t)r * NF + i] = tf32r(e);
        }
    }

    __shared__ float red[8][256];
    #pragma unroll
    for (int r = 0; r < 8; ++r) red[r][tid] = part[r];
    __syncthreads();
    #pragma unroll
    for (int s = 128; s > 0; s >>= 1) {
        if (tid < s) {
            #pragma unroll
            for (int r = 0; r < 8; ++r) red[r][tid] += red[r][tid + s];
        }
        __syncthreads();
    }
    if (tid < 8) g_iden[b * NQ + m0 + tid] = 1.f / red[tid][0];
}

// ---- Kernel 3: V transpose to [b][c][k], tf32-rounded ----
__global__ void transpose_v(const float* __restrict__ v) {
    __shared__ float tile[32][33];
    const int b = blockIdx.z, k0 = blockIdx.x << 5, c0 = blockIdx.y << 5;
    const int x = threadIdx.x, y = threadIdx.y;
    const float* vb = v + ((size_t)b * NF + k0) * CDIM + c0;
    #pragma unroll
    for (int j = 0; j < 32; j += 8) tile[y + j][x] = vb[(size_t)(y + j) * CDIM + x];
    __syncthreads();
    float* o = g_vt + ((size_t)b * CDIM + c0) * NF + k0;
    #pragma unroll
    for (int j = 0; j < 32; j += 8) o[(size_t)(y + j) * NF + x] = tf32r(tile[x][y + j]);
}

// ---- Kernel 4: tf32 mma.sync GEMM, 8 warps (2/SMSP), warp tile 64x32 ----
__global__ void __launch_bounds__(256, 1) gemm_kernel(float* __restrict__ out) {
    extern __shared__ float sm[];
    const uint32_t sbase = smem_u32(sm);
    const int b = blockIdx.z;
    const int n0 = blockIdx.x * BN;
    const int m0 = blockIdx.y * BM;
    const int tid = threadIdx.x, lane = tid & 31, wid = tid >> 5;
    const int warp_m = wid & 1, warp_n = wid >> 1;   // 2 x 4 warps

    const float* __restrict__ Ag = g_p + ((size_t)b * NQ + m0) * NF;
    const float* __restrict__ Bg = g_vt + ((size_t)b * CDIM + n0) * NF;

    auto load_stage = [&](int s, int k0) {
        const uint32_t As = sbase + (uint32_t)s * STAGE_FLOATS * 4;
        const uint32_t Bs = As + TILE_FLOATS * 4;
        #pragma unroll
        for (int j = 0; j < 4; ++j) {
            int flat = tid + 256 * j;          // 0..1023
            int row = flat >> 3, k4 = flat & 7;
            cp_async16(As + (uint32_t)(row * LDT + k4 * 4) * 4,
                       Ag + (size_t)row * NF + k0 + k4 * 4);
        }
        #pragma unroll
        for (int j = 0; j < 4; ++j) {
            int flat = tid + 256 * j;
            int row = flat >> 3, k4 = flat & 7;
            cp_async16(Bs + (uint32_t)(row * LDT + k4 * 4) * 4,
                       Bg + (size_t)row * NF + k0 + k4 * 4);
        }
        CP_COMMIT();
    };

    #pragma unroll
    for (int s = 0; s < STAGES; ++s) load_stage(s, s * BK);

    float acc[4][4][4];
    #pragma unroll
    for (int ma = 0; ma < 4; ++ma)
        #pragma unroll
        for (int na = 0; na < 4; ++na)
            #pragma unroll
            for (int r = 0; r < 4; ++r) acc[ma][na][r] = 0.f;

    const int g = lane >> 2, t = lane & 3;

    for (int c = 0; c < NCH; ++c) {
        CP_WAIT2();
        __syncthreads();
        const int s = c % STAGES;
        const uint32_t As = sbase + (uint32_t)s * STAGE_FLOATS * 4;
        const uint32_t Bs = As + TILE_FLOATS * 4;

        #pragma unroll
        for (int ks = 0; ks < BK / 8; ++ks) {
            uint32_t af[4][4], bf[4][2];
            #pragma unroll
            for (int ma = 0; ma < 4; ++ma) {
                const int row = warp_m * 64 + ma * 16 + g;
                const int col = ks * 8 + t;
                af[ma][0] = lds32(As + (uint32_t)(row * LDT + col) * 4);
                af[ma][1] = lds32(As + (uint32_t)((row + 8) * LDT + col) * 4);
                af[ma][2] = lds32(As + (uint32_t)(row * LDT + col + 4) * 4);
                af[ma][3] = lds32(As + (uint32_t)((row + 8) * LDT + col + 4) * 4);
            }
            #pragma unroll
            for (int na = 0; na < 4; ++na) {
                const int nrow = warp_n * 32 + na * 8 + g;
                const int kk = ks * 8 + t;
                bf[na][0] = lds32(Bs + (uint32_t)(nrow * LDT + kk) * 4);
                bf[na][1] = lds32(Bs + (uint32_t)(nrow * LDT + kk + 4) * 4);
            }
            #pragma unroll
            for (int ma = 0; ma < 4; ++ma)
                #pragma unroll
                for (int na = 0; na < 4; ++na)
                    mma_tf32(acc[ma][na], af[ma], bf[na]);
        }
        __syncthreads();
        if (c + STAGES < NCH) load_stage(s, (c + STAGES) * BK);
        else CP_COMMIT();
    }

    #pragma unroll
    for (int ma = 0; ma < 4; ++ma) {
        const int r0 = m0 + warp_m * 64 + ma * 16 + g;
        const int r1 = r0 + 8;
        const float i0 = g_iden[b * NQ + r0];
        const float i1 = g_iden[b * NQ + r1];
        #pragma unroll
        for (int na = 0; na < 4; ++na) {
            const int n = n0 + warp_n * 32 + na * 8 + 2 * t;
            float2 o0 = make_float2(acc[ma][na][0] * i0, acc[ma][na][1] * i0);
            float2 o1 = make_float2(acc[ma][na][2] * i1, acc[ma][na][3] * i1);
            *reinterpret_cast<float2*>(out + ((size_t)b * NQ + r0) * CDIM + n) = o0;
            *reinterpret_cast<float2*>(out + ((size_t)b * NQ + r1) * CDIM + n) = o1;
        }
    }
}

extern "C" void kernel_launch(void* const* d_in, const int* in_sizes, int n_in,
                              void* d_out, int out_size) {
    const float* q  = (const float*)d_in[0];
    const float* k  = (const float*)d_in[1];
    const float* v  = (const float*)d_in[2];
    const float* W1 = (const float*)d_in[3];
    const float* b1 = (const float*)d_in[4];
    const float* W2 = (const float*)d_in[5];
    const float* b2 = (const float*)d_in[6];
    float* out = (float*)d_out;

    const int total = NBATCH * (NQ + NF);
    proj_kernel<<<(total + 255) / 256, 256>>>(q, k, W1, b1, W2, b2);

    transpose_v<<<dim3(NF / 32, CDIM / 32, NBATCH), dim3(32, 8)>>>(v);

    exp_kernel<<<dim3(NQ / 8, NBATCH), 256>>>();

    cudaFuncSetAttribute(gemm_kernel, cudaFuncAttributeMaxDynamicSharedMemorySize, GEMM_SMEM);
    gemm_kernel<<<dim3(CDIM / BN, NQ / BM, NBATCH), 256, GEMM_SMEM>>>(out);
}

// round 9
// speedup vs baseline: 1.6879x; 1.6879x over previous
#include <cuda_runtime.h>
#include <cuda_fp16.h>
#include <cstdint>

#define NBATCH 4
#define NQ 2048
#define NF 16384
#define CDIM 768
#define SCALEF 0.57735026918962576f

// ---- GEMM tiling (fp16 operands, fp32 accum) ----
#define BM 128
#define BN 128
#define BK 32
#define STAGES 4
#define LDT 40                       // padded row length in halves
#define TILE_HALVES (BM * LDT)       // 5120
#define STAGE_BYTES (2 * TILE_HALVES * 2)   // A + B = 20480
#define GEMM_SMEM (STAGES * STAGE_BYTES)    // 81920
#define NCH (NF / BK)                // 512

__device__ __align__(16) float4 g_qp[NBATCH * NQ];
__device__ __align__(16) float4 g_kp[NBATCH * NF];
__device__ __align__(16) __half g_p[(size_t)NBATCH * NQ * NF];     // exp(s-m), fp16
__device__ __align__(16) __half g_vt[(size_t)NBATCH * CDIM * NF];  // V^T, fp16
__device__ float g_iden[NBATCH * NQ];

__device__ __forceinline__ uint32_t smem_u32(const void* p) {
    uint32_t a;
    asm("{ .reg .u64 t; cvta.to.shared.u64 t, %1; cvt.u32.u64 %0, t; }" : "=r"(a) : "l"(p));
    return a;
}
__device__ __forceinline__ uint32_t lds32(uint32_t a) {
    uint32_t v;
    asm volatile("ld.shared.b32 %0, [%1];" : "=r"(v) : "r"(a));
    return v;
}
__device__ __forceinline__ void cp_async16(uint32_t saddr, const void* gaddr) {
    asm volatile("cp.async.cg.shared.global [%0], [%1], 16;" :: "r"(saddr), "l"(gaddr));
}
#define CP_COMMIT() asm volatile("cp.async.commit_group;" ::: "memory")
#define CP_WAIT()   asm volatile("cp.async.wait_group %0;" :: "n"(STAGES - 1) : "memory")

__device__ __forceinline__ void mma_f16(float* d, const uint32_t* a, const uint32_t* b) {
    asm volatile(
        "mma.sync.aligned.m16n8k16.row.col.f32.f16.f16.f32 "
        "{%0,%1,%2,%3}, {%4,%5,%6,%7}, {%8,%9}, {%0,%1,%2,%3};"
        : "+f"(d[0]), "+f"(d[1]), "+f"(d[2]), "+f"(d[3])
        : "r"(a[0]), "r"(a[1]), "r"(a[2]), "r"(a[3]), "r"(b[0]), "r"(b[1]));
}

// ---- Kernel 1: 3x3 projections + ReLU (q pre-scaled by 1/sqrt(3)) ----
__global__ void proj_kernel(const float* __restrict__ q, const float* __restrict__ k,
                            const float* __restrict__ W1, const float* __restrict__ b1,
                            const float* __restrict__ W2, const float* __restrict__ b2) {
    int i = blockIdx.x * blockDim.x + threadIdx.x;
    const int nq = NBATCH * NQ, nf = NBATCH * NF;
    if (i < nq) {
        float x0 = q[3 * i], x1 = q[3 * i + 1], x2 = q[3 * i + 2];
        float4 o;
        o.x = SCALEF * fmaxf(0.f, fmaf(W1[0], x0, fmaf(W1[1], x1, fmaf(W1[2], x2, b1[0]))));
        o.y = SCALEF * fmaxf(0.f, fmaf(W1[3], x0, fmaf(W1[4], x1, fmaf(W1[5], x2, b1[1]))));
        o.z = SCALEF * fmaxf(0.f, fmaf(W1[6], x0, fmaf(W1[7], x1, fmaf(W1[8], x2, b1[2]))));
        o.w = 0.f;
        g_qp[i] = o;
    } else if (i < nq + nf) {
        int j = i - nq;
        float x0 = k[3 * j], x1 = k[3 * j + 1], x2 = k[3 * j + 2];
        float4 o;
        o.x = fmaxf(0.f, fmaf(W2[0], x0, fmaf(W2[1], x1, fmaf(W2[2], x2, b2[0]))));
        o.y = fmaxf(0.f, fmaf(W2[3], x0, fmaf(W2[4], x1, fmaf(W2[5], x2, b2[1]))));
        o.z = fmaxf(0.f, fmaf(W2[6], x0, fmaf(W2[7], x1, fmaf(W2[8], x2, b2[2]))));
        o.w = 0.f;
        g_kp[j] = o;
    }
}

// ---- Kernel 2: row max, then E = exp(s - m) in fp16, 1/den in fp32 ----
// Grid (NQ/8, NBATCH), 256 threads, 8 query rows per block.
__global__ void __launch_bounds__(256) exp_kernel() {
    const int m0 = blockIdx.x * 8, b = blockIdx.y;
    const int tid = threadIdx.x;
    float4 qv[8];
    #pragma unroll
    for (int r = 0; r < 8; ++r) qv[r] = g_qp[b * NQ + m0 + r];
    const float4* __restrict__ kp = g_kp + b * NF;
    __half* __restrict__ pbase = g_p + ((size_t)b * NQ + m0) * NF;

    __shared__ float red[8][256];

    // Pass 1: per-row max of scores
    float mx[8];
    #pragma unroll
    for (int r = 0; r < 8; ++r) mx[r] = -1e30f;
    for (int i = tid; i < NF; i += 256) {
        float4 kv = kp[i];
        #pragma unroll
        for (int r = 0; r < 8; ++r)
            mx[r] = fmaxf(mx[r], qv[r].x * kv.x + qv[r].y * kv.y + qv[r].z * kv.z);
    }
    #pragma unroll
    for (int r = 0; r < 8; ++r) red[r][tid] = mx[r];
    __syncthreads();
    #pragma unroll
    for (int s = 128; s > 0; s >>= 1) {
        if (tid < s) {
            #pragma unroll
            for (int r = 0; r < 8; ++r)
                red[r][tid] = fmaxf(red[r][tid], red[r][tid + s]);
        }
        __syncthreads();
    }
    #pragma unroll
    for (int r = 0; r < 8; ++r) mx[r] = red[r][0];
    __syncthreads();

    // Pass 2: exp(s - m) -> fp16 store; fp32 denominator
    float part[8];
    #pragma unroll
    for (int r = 0; r < 8; ++r) part[r] = 0.f;
    for (int i = tid; i < NF; i += 256) {
        float4 kv = kp[i];
        #pragma unroll
        for (int r = 0; r < 8; ++r) {
            float e = __expf(qv[r].x * kv.x + qv[r].y * kv.y + qv[r].z * kv.z - mx[r]);
            part[r] += e;
            pbase[(size_t)r * NF + i] = __float2half_rn(e);
        }
    }
    #pragma unroll
    for (int r = 0; r < 8; ++r) red[r][tid] = part[r];
    __syncthreads();
    #pragma unroll
    for (int s = 128; s > 0; s >>= 1) {
        if (tid < s) {
            #pragma unroll
            for (int r = 0; r < 8; ++r) red[r][tid] += red[r][tid + s];
        }
        __syncthreads();
    }
    if (tid < 8) g_iden[b * NQ + m0 + tid] = 1.f / red[tid][0];
}

// ---- Kernel 3: V transpose to [b][c][k], fp16 ----
__global__ void transpose_v(const float* __restrict__ v) {
    __shared__ float tile[32][33];
    const int b = blockIdx.z, k0 = blockIdx.x << 5, c0 = blockIdx.y << 5;
    const int x = threadIdx.x, y = threadIdx.y;
    const float* vb = v + ((size_t)b * NF + k0) * CDIM + c0;
    #pragma unroll
    for (int j = 0; j < 32; j += 8) tile[y + j][x] = vb[(size_t)(y + j) * CDIM + x];
    __syncthreads();
    __half* o = g_vt + ((size_t)b * CDIM + c0) * NF + k0;
    #pragma unroll
    for (int j = 0; j < 32; j += 8) o[(size_t)(y + j) * NF + x] = __float2half_rn(tile[x][y + j]);
}

// ---- Kernel 4: fp16 mma.sync GEMM, 4 warps, warp tile 64x64, 2 CTAs/SM ----
__global__ void __launch_bounds__(128, 2) gemm_kernel(float* __restrict__ out) {
    extern __shared__ __half sm[];
    const uint32_t sbase = smem_u32(sm);
    const int b = blockIdx.z;
    const int n0 = blockIdx.x * BN;
    const int m0 = blockIdx.y * BM;
    const int tid = threadIdx.x, lane = tid & 31, wid = tid >> 5;
    const int warp_m = wid & 1, warp_n = wid >> 1;   // 2 x 2 warps

    const __half* __restrict__ Ag = g_p + ((size_t)b * NQ + m0) * NF;
    const __half* __restrict__ Bg = g_vt + ((size_t)b * CDIM + n0) * NF;

    // stage loader: A/B tiles 128 x 32 halves, 4 x 16B chunks per row
    auto load_stage = [&](int s, int k0) {
        const uint32_t As = sbase + (uint32_t)s * STAGE_BYTES;
        const uint32_t Bs = As + TILE_HALVES * 2;
        #pragma unroll
        for (int j = 0; j < 4; ++j) {
            int flat = tid + 128 * j;          // 0..511
            int row = flat >> 2, k8 = flat & 3;
            cp_async16(As + (uint32_t)(row * LDT + k8 * 8) * 2,
                       Ag + (size_t)row * NF + k0 + k8 * 8);
        }
        #pragma unroll
        for (int j = 0; j < 4; ++j) {
            int flat = tid + 128 * j;
            int row = flat >> 2, k8 = flat & 3;
            cp_async16(Bs + (uint32_t)(row * LDT + k8 * 8) * 2,
                       Bg + (size_t)row * NF + k0 + k8 * 8);
        }
        CP_COMMIT();
    };

    #pragma unroll
    for (int s = 0; s < STAGES; ++s) load_stage(s, s * BK);

    float acc[4][8][4];
    #pragma unroll
    for (int ma = 0; ma < 4; ++ma)
        #pragma unroll
        for (int na = 0; na < 8; ++na)
            #pragma unroll
            for (int r = 0; r < 4; ++r) acc[ma][na][r] = 0.f;

    const int g = lane >> 2, t = lane & 3;

    for (int c = 0; c < NCH; ++c) {
        CP_WAIT();
        __syncthreads();
        const int s = c % STAGES;
        const uint32_t As = sbase + (uint32_t)s * STAGE_BYTES;
        const uint32_t Bs = As + TILE_HALVES * 2;

        #pragma unroll
        for (int ks = 0; ks < BK / 16; ++ks) {
            const int k0h = ks * 16;
            uint32_t af[4][4], bf[8][2];
            #pragma unroll
            for (int ma = 0; ma < 4; ++ma) {
                const int row = warp_m * 64 + ma * 16 + g;
                af[ma][0] = lds32(As + (uint32_t)(row * LDT + k0h + 2 * t) * 2);
                af[ma][1] = lds32(As + (uint32_t)((row + 8) * LDT + k0h + 2 * t) * 2);
                af[ma][2] = lds32(As + (uint32_t)(row * LDT + k0h + 2 * t + 8) * 2);
                af[ma][3] = lds32(As + (uint32_t)((row + 8) * LDT + k0h + 2 * t + 8) * 2);
            }
            #pragma unroll
            for (int na = 0; na < 8; ++na) {
                const int n = warp_n * 64 + na * 8 + g;
                bf[na][0] = lds32(Bs + (uint32_t)(n * LDT + k0h + 2 * t) * 2);
                bf[na][1] = lds32(Bs + (uint32_t)(n * LDT + k0h + 2 * t + 8) * 2);
            }
            #pragma unroll
            for (int ma = 0; ma < 4; ++ma)
                #pragma unroll
                for (int na = 0; na < 8; ++na)
                    mma_f16(acc[ma][na], af[ma], bf[na]);
        }
        __syncthreads();
        if (c + STAGES < NCH) load_stage(s, (c + STAGES) * BK);
        else CP_COMMIT();
    }

    // epilogue: scale by 1/den, float2 stores
    #pragma unroll
    for (int ma = 0; ma < 4; ++ma) {
        const int r0 = m0 + warp_m * 64 + ma * 16 + g;
        const int r1 = r0 + 8;
        const float i0 = g_iden[b * NQ + r0];
        const float i1 = g_iden[b * NQ + r1];
        #pragma unroll
        for (int na = 0; na < 8; ++na) {
            const int n = n0 + warp_n * 64 + na * 8 + 2 * t;
            float2 o0 = make_float2(acc[ma][na][0] * i0, acc[ma][na][1] * i0);
            float2 o1 = make_float2(acc[ma][na][2] * i1, acc[ma][na][3] * i1);
            *reinterpret_cast<float2*>(out + ((size_t)b * NQ + r0) * CDIM + n) = o0;
            *reinterpret_cast<float2*>(out + ((size_t)b * NQ + r1) * CDIM + n) = o1;
        }
    }
}

extern "C" void kernel_launch(void* const* d_in, const int* in_sizes, int n_in,
                              void* d_out, int out_size) {
    const float* q  = (const float*)d_in[0];
    const float* k  = (const float*)d_in[1];
    const float* v  = (const float*)d_in[2];
    const float* W1 = (const float*)d_in[3];
    const float* b1 = (const float*)d_in[4];
    const float* W2 = (const float*)d_in[5];
    const float* b2 = (const float*)d_in[6];
    float* out = (float*)d_out;

    const int total = NBATCH * (NQ + NF);
    proj_kernel<<<(total + 255) / 256, 256>>>(q, k, W1, b1, W2, b2);

    transpose_v<<<dim3(NF / 32, CDIM / 32, NBATCH), dim3(32, 8)>>>(v);

    exp_kernel<<<dim3(NQ / 8, NBATCH), 256>>>();

    cudaFuncSetAttribute(gemm_kernel, cudaFuncAttributeMaxDynamicSharedMemorySize, GEMM_SMEM);
    gemm_kernel<<<dim3(CDIM / BN, NQ / BM, NBATCH), 128, GEMM_SMEM>>>(out);
}

// round 10
// speedup vs baseline: 2.2811x; 1.3514x over previous
#include <cuda_runtime.h>
#include <cuda_fp16.h>
#include <cstdint>

#define NBATCH 4
#define NQ 2048
#define NF 16384
#define CDIM 768
#define SCALEF 0.57735026918962576f

// ---- GEMM tiling (fp16 operands, fp32 accum), split-K ----
#define BM 128
#define BN 128
#define BK 32
#define SPLITK 2
#define KPS (NF / SPLITK)            // 8192
#define NCH (KPS / BK)               // 256
#define STAGES 4
#define LDT 40                       // padded row length in halves (80B: conflict-free)
#define TILE_HALVES (BM * LDT)
#define STAGE_BYTES (2 * TILE_HALVES * 2)
#define GEMM_SMEM (STAGES * STAGE_BYTES)     // 81920

__device__ __align__(16) float4 g_qp[NBATCH * NQ];
__device__ __align__(16) float4 g_kp[NBATCH * NF];
__device__ __align__(16) __half g_p[(size_t)NBATCH * NQ * NF];
__device__ __align__(16) __half g_vt[(size_t)NBATCH * CDIM * NF];
__device__ __align__(16) float g_part[(size_t)SPLITK * NBATCH * NQ * CDIM];
__device__ float g_iden[NBATCH * NQ];

__device__ __forceinline__ uint32_t smem_u32(const void* p) {
    uint32_t a;
    asm("{ .reg .u64 t; cvta.to.shared.u64 t, %1; cvt.u32.u64 %0, t; }" : "=r"(a) : "l"(p));
    return a;
}
__device__ __forceinline__ void cp_async16(uint32_t saddr, const void* gaddr) {
    asm volatile("cp.async.cg.shared.global [%0], [%1], 16;" :: "r"(saddr), "l"(gaddr));
}
#define CP_COMMIT() asm volatile("cp.async.commit_group;" ::: "memory")
#define CP_WAIT()   asm volatile("cp.async.wait_group %0;" :: "n"(STAGES - 2) : "memory")

__device__ __forceinline__ void ldm_x4(uint32_t& r0, uint32_t& r1, uint32_t& r2,
                                       uint32_t& r3, uint32_t a) {
    asm volatile("ldmatrix.sync.aligned.m8n8.x4.shared.b16 {%0,%1,%2,%3}, [%4];"
                 : "=r"(r0), "=r"(r1), "=r"(r2), "=r"(r3) : "r"(a));
}
__device__ __forceinline__ void mma_f16(float* d, const uint32_t* a, const uint32_t* b) {
    asm volatile(
        "mma.sync.aligned.m16n8k16.row.col.f32.f16.f16.f32 "
        "{%0,%1,%2,%3}, {%4,%5,%6,%7}, {%8,%9}, {%0,%1,%2,%3};"
        : "+f"(d[0]), "+f"(d[1]), "+f"(d[2]), "+f"(d[3])
        : "r"(a[0]), "r"(a[1]), "r"(a[2]), "r"(a[3]), "r"(b[0]), "r"(b[1]));
}

// ---- Kernel 1: 3x3 projections + ReLU (q pre-scaled by 1/sqrt(3)) ----
__global__ void proj_kernel(const float* __restrict__ q, const float* __restrict__ k,
                            const float* __restrict__ W1, const float* __restrict__ b1,
                            const float* __restrict__ W2, const float* __restrict__ b2) {
    int i = blockIdx.x * blockDim.x + threadIdx.x;
    const int nq = NBATCH * NQ, nf = NBATCH * NF;
    if (i < nq) {
        float x0 = q[3 * i], x1 = q[3 * i + 1], x2 = q[3 * i + 2];
        float4 o;
        o.x = SCALEF * fmaxf(0.f, fmaf(W1[0], x0, fmaf(W1[1], x1, fmaf(W1[2], x2, b1[0]))));
        o.y = SCALEF * fmaxf(0.f, fmaf(W1[3], x0, fmaf(W1[4], x1, fmaf(W1[5], x2, b1[1]))));
        o.z = SCALEF * fmaxf(0.f, fmaf(W1[6], x0, fmaf(W1[7], x1, fmaf(W1[8], x2, b1[2]))));
        o.w = 0.f;
        g_qp[i] = o;
    } else if (i < nq + nf) {
        int j = i - nq;
        float x0 = k[3 * j], x1 = k[3 * j + 1], x2 = k[3 * j + 2];
        float4 o;
        o.x = fmaxf(0.f, fmaf(W2[0], x0, fmaf(W2[1], x1, fmaf(W2[2], x2, b2[0]))));
        o.y = fmaxf(0.f, fmaf(W2[3], x0, fmaf(W2[4], x1, fmaf(W2[5], x2, b2[1]))));
        o.z = fmaxf(0.f, fmaf(W2[6], x0, fmaf(W2[7], x1, fmaf(W2[8], x2, b2[2]))));
        o.w = 0.f;
        g_kp[j] = o;
    }
}

// ---- Kernel 2: row max, then E = exp(s-m) fp16 (half2 stores), 1/den fp32 ----
__global__ void __launch_bounds__(256) exp_kernel() {
    const int m0 = blockIdx.x * 8, b = blockIdx.y;
    const int tid = threadIdx.x;
    float4 qv[8];
    #pragma unroll
    for (int r = 0; r < 8; ++r) qv[r] = g_qp[b * NQ + m0 + r];
    const float4* __restrict__ kp = g_kp + b * NF;
    __half* __restrict__ pbase = g_p + ((size_t)b * NQ + m0) * NF;

    __shared__ float red[8][256];

    float mx[8];
    #pragma unroll
    for (int r = 0; r < 8; ++r) mx[r] = -1e30f;
    for (int i = tid; i < NF; i += 256) {
        float4 kv = kp[i];
        #pragma unroll
        for (int r = 0; r < 8; ++r)
            mx[r] = fmaxf(mx[r], qv[r].x * kv.x + qv[r].y * kv.y + qv[r].z * kv.z);
    }
    #pragma unroll
    for (int r = 0; r < 8; ++r) red[r][tid] = mx[r];
    __syncthreads();
    #pragma unroll
    for (int s = 128; s > 0; s >>= 1) {
        if (tid < s) {
            #pragma unroll
            for (int r = 0; r < 8; ++r)
                red[r][tid] = fmaxf(red[r][tid], red[r][tid + s]);
        }
        __syncthreads();
    }
    #pragma unroll
    for (int r = 0; r < 8; ++r) mx[r] = red[r][0];
    __syncthreads();

    float part[8];
    #pragma unroll
    for (int r = 0; r < 8; ++r) part[r] = 0.f;
    for (int i = 2 * tid; i < NF; i += 512) {
        float4 kva = kp[i], kvb = kp[i + 1];
        #pragma unroll
        for (int r = 0; r < 8; ++r) {
            float ea = __expf(qv[r].x * kva.x + qv[r].y * kva.y + qv[r].z * kva.z - mx[r]);
            float eb = __expf(qv[r].x * kvb.x + qv[r].y * kvb.y + qv[r].z * kvb.z - mx[r]);
            part[r] += ea + eb;
            *reinterpret_cast<__half2*>(pbase + (size_t)r * NF + i) =
                __floats2half2_rn(ea, eb);
        }
    }
    #pragma unroll
    for (int r = 0; r < 8; ++r) red[r][tid] = part[r];
    __syncthreads();
    #pragma unroll
    for (int s = 128; s > 0; s >>= 1) {
        if (tid < s) {
            #pragma unroll
            for (int r = 0; r < 8; ++r) red[r][tid] += red[r][tid + s];
        }
        __syncthreads();
    }
    if (tid < 8) g_iden[b * NQ + m0 + tid] = 1.f / red[tid][0];
}

// ---- Kernel 3: V transpose to [b][c][k], fp16, half2 stores ----
__global__ void transpose_v(const float* __restrict__ v) {
    __shared__ float tile[32][33];
    const int b = blockIdx.z, k0 = blockIdx.x << 5, c0 = blockIdx.y << 5;
    const int x = threadIdx.x, y = threadIdx.y;
    const float* vb = v + ((size_t)b * NF + k0) * CDIM + c0;
    #pragma unroll
    for (int j = 0; j < 32; j += 8) tile[y + j][x] = vb[(size_t)(y + j) * CDIM + x];
    __syncthreads();
    const int flat = y * 32 + x;
    const int cl = flat >> 4, k2 = (flat & 15) * 2;
    __half* o = g_vt + ((size_t)b * CDIM + c0) * NF + k0;
    #pragma unroll
    for (int p = 0; p < 2; ++p) {
        const int c = cl + p * 16;
        *reinterpret_cast<__half2*>(o + (size_t)c * NF + k2) =
            __floats2half2_rn(tile[k2][c], tile[k2 + 1][c]);
    }
}

// ---- Kernel 4: fp16 mma GEMM, split-K, ldmatrix, single-barrier pipeline ----
// Grid (6, 16, NBATCH*SPLITK). 128 threads, warp tile 64x64.
__global__ void __launch_bounds__(128, 2) gemm_kernel() {
    extern __shared__ __half sm[];
    const uint32_t sbase = smem_u32(sm);
    const int b = blockIdx.z >> 1, split = blockIdx.z & 1;
    const int n0 = blockIdx.x * BN;
    const int m0 = blockIdx.y * BM;
    const int tid = threadIdx.x, lane = tid & 31, wid = tid >> 5;
    const int warp_m = wid & 1, warp_n = wid >> 1;

    const __half* __restrict__ Ag =
        g_p + ((size_t)b * NQ + m0) * NF + (size_t)split * KPS;
    const __half* __restrict__ Bg =
        g_vt + ((size_t)b * CDIM + n0) * NF + (size_t)split * KPS;

    auto load_stage = [&](int s, int k0) {
        const uint32_t As = sbase + (uint32_t)s * STAGE_BYTES;
        const uint32_t Bs = As + TILE_HALVES * 2;
        #pragma unroll
        for (int j = 0; j < 4; ++j) {
            int flat = tid + 128 * j;
            int row = flat >> 2, k8 = flat & 3;
            cp_async16(As + (uint32_t)(row * LDT + k8 * 8) * 2,
                       Ag + (size_t)row * NF + k0 + k8 * 8);
        }
        #pragma unroll
        for (int j = 0; j < 4; ++j) {
            int flat = tid + 128 * j;
            int row = flat >> 2, k8 = flat & 3;
            cp_async16(Bs + (uint32_t)(row * LDT + k8 * 8) * 2,
                       Bg + (size_t)row * NF + k0 + k8 * 8);
        }
        CP_COMMIT();
    };

    // prologue: STAGES-1 stages in flight
    #pragma unroll
    for (int s = 0; s < STAGES - 1; ++s) load_stage(s, s * BK);

    float acc[4][8][4];
    #pragma unroll
    for (int ma = 0; ma < 4; ++ma)
        #pragma unroll
        for (int na = 0; na < 8; ++na)
            #pragma unroll
            for (int r = 0; r < 4; ++r) acc[ma][na][r] = 0.f;

    // ldmatrix per-lane offsets
    const int a_row = lane & 15, a_kh = (lane >> 4) << 3;
    const int b_nrow = ((lane >> 4) << 3) + (lane & 7), b_kh = ((lane >> 3) & 1) << 3;

    for (int c = 0; c < NCH; ++c) {
        CP_WAIT();             // stage c landed
        __syncthreads();       // all warps done with stage c-1
        if (c + STAGES - 1 < NCH)
            load_stage((c + STAGES - 1) % STAGES, (c + STAGES - 1) * BK);
        else
            CP_COMMIT();       // keep group accounting aligned

        const int s = c % STAGES;
        const uint32_t As = sbase + (uint32_t)s * STAGE_BYTES;
        const uint32_t Bs = As + TILE_HALVES * 2;

        #pragma unroll
        for (int ks = 0; ks < BK / 16; ++ks) {
            uint32_t af[4][4], bf[8][2];
            #pragma unroll
            for (int ma = 0; ma < 4; ++ma)
                ldm_x4(af[ma][0], af[ma][1], af[ma][2], af[ma][3],
                       As + (uint32_t)((warp_m * 64 + ma * 16 + a_row) * LDT +
                                       ks * 16 + a_kh) * 2);
            #pragma unroll
            for (int n8 = 0; n8 < 4; ++n8)
                ldm_x4(bf[2 * n8][0], bf[2 * n8][1], bf[2 * n8 + 1][0], bf[2 * n8 + 1][1],
                       Bs + (uint32_t)((warp_n * 64 + n8 * 16 + b_nrow) * LDT +
                                       ks * 16 + b_kh) * 2);
            #pragma unroll
            for (int ma = 0; ma < 4; ++ma)
                #pragma unroll
                for (int na = 0; na < 8; ++na)
                    mma_f16(acc[ma][na], af[ma], bf[na]);
        }
    }

    // epilogue: raw partials (iden applied in combine)
    const int g = lane >> 2, t = lane & 3;
    float* pout = g_part + ((size_t)(split * NBATCH + b) * NQ + m0) * CDIM + n0;
    #pragma unroll
    for (int ma = 0; ma < 4; ++ma) {
        const int r0 = warp_m * 64 + ma * 16 + g;
        #pragma unroll
        for (int na = 0; na < 8; ++na) {
            const int n = warp_n * 64 + na * 8 + 2 * t;
            *reinterpret_cast<float2*>(pout + (size_t)r0 * CDIM + n) =
                make_float2(acc[ma][na][0], acc[ma][na][1]);
            *reinterpret_cast<float2*>(pout + (size_t)(r0 + 8) * CDIM + n) =
                make_float2(acc[ma][na][2], acc[ma][na][3]);
        }
    }
}

// ---- Kernel 5: combine split-K partials, scale by 1/den ----
__global__ void combine_kernel(float* __restrict__ out) {
    const size_t i = (size_t)blockIdx.x * blockDim.x + threadIdx.x;
    const size_t total4 = (size_t)NBATCH * NQ * CDIM / 4;
    if (i >= total4) return;
    const size_t rowi = i / (CDIM / 4);
    float4 p0 = reinterpret_cast<const float4*>(g_part)[i];
    float4 p1 = reinterpret_cast<const float4*>(g_part)[i + total4];
    const float inv = g_iden[rowi];
    float4 o;
    o.x = (p0.x + p1.x) * inv;
    o.y = (p0.y + p1.y) * inv;
    o.z = (p0.z + p1.z) * inv;
    o.w = (p0.w + p1.w) * inv;
    reinterpret_cast<float4*>(out)[i] = o;
}

extern "C" void kernel_launch(void* const* d_in, const int* in_sizes, int n_in,
                              void* d_out, int out_size) {
    const float* q  = (const float*)d_in[0];
    const float* k  = (const float*)d_in[1];
    const float* v  = (const float*)d_in[2];
    const float* W1 = (const float*)d_in[3];
    const float* b1 = (const float*)d_in[4];
    const float* W2 = (const float*)d_in[5];
    const float* b2 = (const float*)d_in[6];
    float* out = (float*)d_out;

    const int total = NBATCH * (NQ + NF);
    proj_kernel<<<(total + 255) / 256, 256>>>(q, k, W1, b1, W2, b2);

    transpose_v<<<dim3(NF / 32, CDIM / 32, NBATCH), dim3(32, 8)>>>(v);

    exp_kernel<<<dim3(NQ / 8, NBATCH), 256>>>();

    cudaFuncSetAttribute(gemm_kernel, cudaFuncAttributeMaxDynamicSharedMemorySize, GEMM_SMEM);
    gemm_kernel<<<dim3(CDIM / BN, NQ / BM, NBATCH * SPLITK), 128, GEMM_SMEM>>>();

    const int total4 = NBATCH * NQ * CDIM / 4;
    combine_kernel<<<(total4 + 255) / 256, 256>>>(out);
}